// round 1
// baseline (speedup 1.0000x reference)
#include <cuda_runtime.h>
#include <math.h>

#define T_CTX 100000
#define H 256
#define BM 64           // rows per GEMM block
#define KT 32           // K tile
#define E_CHUNK 512     // rows per ct block
#define NB_E ((T_CTX + E_CHUNK - 1) / E_CHUNK)   // 196

// Scratch (static device globals: allocation-free per harness rules)
__device__ float g_At[T_CTX];
__device__ float g_proj[H];
__device__ float g_lse;
__device__ float g_ct_partial[NB_E][H];

// ---------------------------------------------------------------------------
// proj = hc @ W1^T   (1x256) — tiny
// ---------------------------------------------------------------------------
__global__ void proj_kernel(const float* __restrict__ hc,
                            const float* __restrict__ W1) {
    int j = threadIdx.x;                      // 256 threads
    float s = 0.f;
#pragma unroll 8
    for (int k = 0; k < H; ++k)
        s = fmaf(hc[k], W1[j * H + k], s);
    g_proj[j] = s;
}

// ---------------------------------------------------------------------------
// Fused: At = tanh(inputs @ Wm + proj) @ V
// Block: 64 rows x ALL 256 cols (so the 100MB intermediate never hits HBM).
// 256 threads, each owns a 4x16 register tile (64 fp32 accumulators).
// ---------------------------------------------------------------------------
__global__ __launch_bounds__(256, 2)
void gemm_tanh_kernel(const float* __restrict__ A,    // inputs  T x H
                      const float* __restrict__ Wm,   // H x H
                      const float* __restrict__ V) {  // H
    __shared__ float As[BM][36];     // pad 36: 16B-aligned float4 stores, bank-spread reads
    __shared__ float Bs[KT][H];      // 32 x 256
    __shared__ float red[BM][16];

    const int tid = threadIdx.x;
    const int tx  = tid & 15;        // column group (16 cols each... 16 groups)
    const int ty  = tid >> 4;        // row group (4 rows each)
    const int row0 = blockIdx.x * BM;

    float acc[4][16];
#pragma unroll
    for (int j = 0; j < 4; ++j)
#pragma unroll
        for (int i = 0; i < 16; ++i) acc[j][i] = 0.f;

    for (int k0 = 0; k0 < H; k0 += KT) {
        // Load A tile: 64x32 = 512 float4, 2 per thread
#pragma unroll
        for (int m = 0; m < 2; ++m) {
            int e  = tid + m * 256;
            int r  = e >> 3;
            int kq = e & 7;
            int grow = row0 + r;
            float4 v4 = make_float4(0.f, 0.f, 0.f, 0.f);
            if (grow < T_CTX)
                v4 = *reinterpret_cast<const float4*>(&A[(size_t)grow * H + k0 + kq * 4]);
            *reinterpret_cast<float4*>(&As[r][kq * 4]) = v4;
        }
        // Load B tile: 32x256 = 2048 float4, 8 per thread
#pragma unroll
        for (int m = 0; m < 8; ++m) {
            int e  = tid + m * 256;
            int kr = e >> 6;
            int cq = e & 63;
            *reinterpret_cast<float4*>(&Bs[kr][cq * 4]) =
                *reinterpret_cast<const float4*>(&Wm[(size_t)(k0 + kr) * H + cq * 4]);
        }
        __syncthreads();

#pragma unroll
        for (int kk = 0; kk < KT; ++kk) {
            float a[4], b[16];
#pragma unroll
            for (int j = 0; j < 4; ++j) a[j] = As[ty * 4 + j][kk];
#pragma unroll
            for (int i = 0; i < 4; ++i)
                *reinterpret_cast<float4*>(&b[i * 4]) =
                    *reinterpret_cast<const float4*>(&Bs[kk][tx * 16 + i * 4]);
#pragma unroll
            for (int j = 0; j < 4; ++j)
#pragma unroll
                for (int i = 0; i < 16; ++i)
                    acc[j][i] = fmaf(a[j], b[i], acc[j][i]);
        }
        __syncthreads();
    }

    // Epilogue: + proj, tanh, dot with V, reduce across the 16 column groups
    float pj[16], vv[16];
#pragma unroll
    for (int i = 0; i < 16; ++i) {
        int c = tx * 16 + i;
        pj[i] = g_proj[c];
        vv[i] = V[c];
    }
    float part[4];
#pragma unroll
    for (int j = 0; j < 4; ++j) {
        float s = 0.f;
#pragma unroll
        for (int i = 0; i < 16; ++i)
            s = fmaf(tanhf(acc[j][i] + pj[i]), vv[i], s);
        part[j] = s;
    }
#pragma unroll
    for (int j = 0; j < 4; ++j) red[ty * 4 + j][tx] = part[j];
    __syncthreads();
    if (tid < BM) {
        float s = 0.f;
#pragma unroll
        for (int i = 0; i < 16; ++i) s += red[tid][i];   // fixed order: deterministic
        int grow = row0 + tid;
        if (grow < T_CTX) g_At[grow] = s;
    }
}

// ---------------------------------------------------------------------------
// logsumexp over At (single block, deterministic tree reduce)
// ---------------------------------------------------------------------------
__global__ void softmax_stats_kernel() {
    __shared__ float sm[1024];
    const int tid = threadIdx.x;

    float m = -1e30f;
    for (int t = tid; t < T_CTX; t += 1024) m = fmaxf(m, g_At[t]);
    sm[tid] = m;
    __syncthreads();
    for (int s = 512; s > 0; s >>= 1) {
        if (tid < s) sm[tid] = fmaxf(sm[tid], sm[tid + s]);
        __syncthreads();
    }
    const float gmax = sm[0];
    __syncthreads();

    float sum = 0.f;
    for (int t = tid; t < T_CTX; t += 1024) sum += expf(g_At[t] - gmax);
    sm[tid] = sum;
    __syncthreads();
    for (int s = 512; s > 0; s >>= 1) {
        if (tid < s) sm[tid] += sm[tid + s];
        __syncthreads();
    }
    if (tid == 0) g_lse = gmax + logf(sm[0]);
}

// ---------------------------------------------------------------------------
// alphat = At - lse (written to out) ; per-block ct partials (deterministic)
// ---------------------------------------------------------------------------
__global__ void ct_kernel(const float* __restrict__ A,
                          float* __restrict__ out_alpha) {
    const int b   = blockIdx.x;
    const int t0  = b * E_CHUNK;
    const int tid = threadIdx.x;     // 256 = H
    const float lse = g_lse;
    const int tend = min(t0 + E_CHUNK, T_CTX);

    for (int t = t0 + tid; t < tend; t += 256)
        out_alpha[t] = g_At[t] - lse;

    float acc0 = 0.f, acc1 = 0.f, acc2 = 0.f, acc3 = 0.f;
    int t = t0;
    for (; t + 4 <= tend; t += 4) {
        float w0 = g_At[t]     - lse;
        float w1 = g_At[t + 1] - lse;
        float w2 = g_At[t + 2] - lse;
        float w3 = g_At[t + 3] - lse;
        acc0 = fmaf(w0, A[(size_t)t * H + tid],       acc0);
        acc1 = fmaf(w1, A[(size_t)(t + 1) * H + tid], acc1);
        acc2 = fmaf(w2, A[(size_t)(t + 2) * H + tid], acc2);
        acc3 = fmaf(w3, A[(size_t)(t + 3) * H + tid], acc3);
    }
    for (; t < tend; ++t)
        acc0 = fmaf(g_At[t] - lse, A[(size_t)t * H + tid], acc0);

    g_ct_partial[b][tid] = (acc0 + acc1) + (acc2 + acc3);
}

__global__ void ct_final_kernel(float* __restrict__ out_ct) {
    const int h = threadIdx.x;       // 256
    float s = 0.f;
    for (int b = 0; b < NB_E; ++b) s += g_ct_partial[b][h];  // fixed order
    out_ct[h] = s;
}

// ---------------------------------------------------------------------------
extern "C" void kernel_launch(void* const* d_in, const int* in_sizes, int n_in,
                              void* d_out, int out_size) {
    const float* inputs = (const float*)d_in[0];   // (T, H)
    const float* hc     = (const float*)d_in[1];   // (1, H)
    const float* Wm     = (const float*)d_in[2];   // (H, H)
    const float* V      = (const float*)d_in[3];   // (H, 1)
    const float* W1     = (const float*)d_in[4];   // (H, H)
    float* out = (float*)d_out;                    // [alphat (T) | ct (H)]

    proj_kernel<<<1, 256>>>(hc, W1);
    gemm_tanh_kernel<<<(T_CTX + BM - 1) / BM, 256>>>(inputs, Wm, V);
    softmax_stats_kernel<<<1, 1024>>>();
    ct_kernel<<<NB_E, 256>>>(inputs, out);
    ct_final_kernel<<<1, 256>>>(out + T_CTX);
}

// round 3
// speedup vs baseline: 4.4126x; 4.4126x over previous
#include <cuda_runtime.h>
#include <math.h>
#include <stdint.h>

#define T_CTX 100000
#define H 256

// ---- GEMM tiling (warp mma.sync tf32) ----
#define TILE_M 64                                // rows per CTA
#define NB_G ((T_CTX + TILE_M - 1) / TILE_M)     // 1563
#define KT 32                                    // K chunk
#define NCH (H / KT)                             // 8
#define AS_STRIDE 36                             // padded: bank=(4r+c)&31 -> conflict-free frags

// ---- softmax / ct ----
#define SM_BLOCKS 25
#define E_CHUNK 128
#define NB_E ((T_CTX + E_CHUNK - 1) / E_CHUNK)   // 782

// Scratch (static device globals: allocation-free per harness rules)
__device__ float g_At[T_CTX];
__device__ float g_proj[H];
__device__ float g_WmT[H * H];                   // transposed + tf32-converted
__device__ float g_lse;
__device__ float g_sm_m[SM_BLOCKS];
__device__ float g_sm_s[SM_BLOCKS];
__device__ float g_ct_partial[NB_E][H];

// ===========================================================================
// helpers
// ===========================================================================
__device__ __forceinline__ float tanh_fast(float x) {
    float y;
    asm("tanh.approx.f32 %0, %1;" : "=f"(y) : "f"(x));
    return y;
}
__device__ __forceinline__ uint32_t f2tf32(float x) {
    uint32_t r;
    asm("cvt.rna.tf32.f32 %0, %1;" : "=r"(r) : "f"(x));
    return r;
}
__device__ __forceinline__ void mma_tf32(float d[4], const uint32_t a[4], const uint32_t b[2]) {
    asm volatile(
        "mma.sync.aligned.m16n8k8.row.col.f32.tf32.tf32.f32 "
        "{%0,%1,%2,%3}, {%4,%5,%6,%7}, {%8,%9}, {%0,%1,%2,%3};"
        : "+f"(d[0]), "+f"(d[1]), "+f"(d[2]), "+f"(d[3])
        : "r"(a[0]), "r"(a[1]), "r"(a[2]), "r"(a[3]), "r"(b[0]), "r"(b[1]));
}

// ===========================================================================
// proj = hc @ W1^T  (tiny)
// ===========================================================================
__global__ void proj_kernel(const float* __restrict__ hc, const float* __restrict__ W1) {
    int j = threadIdx.x;
    float s = 0.f;
#pragma unroll 8
    for (int k = 0; k < H; ++k) s = fmaf(hc[k], W1[j * H + k], s);
    g_proj[j] = s;
}

// ===========================================================================
// WmT[n][k] = tf32(Wm[k][n])
// ===========================================================================
__global__ void transpose_kernel(const float* __restrict__ Wm) {
    __shared__ float t[32][33];
    int bx = blockIdx.x & 7, by = blockIdx.x >> 3;
    int x = bx * 32 + threadIdx.x;
#pragma unroll
    for (int j = 0; j < 4; ++j) {
        int y = by * 32 + threadIdx.y + j * 8;
        t[threadIdx.y + j * 8][threadIdx.x] = Wm[y * H + x];
    }
    __syncthreads();
    int x2 = by * 32 + threadIdx.x;
#pragma unroll
    for (int j = 0; j < 4; ++j) {
        int y2 = bx * 32 + threadIdx.y + j * 8;
        g_WmT[y2 * H + x2] = __uint_as_float(f2tf32(t[threadIdx.x][threadIdx.y + j * 8]));
    }
}

// ===========================================================================
// Fused warp-MMA GEMM: At = tanh(inputs @ Wm + proj) @ V
// CTA: 64 rows x 256 cols x K=256. 8 warps = 2 row-groups x 4 col-groups.
// Warp tile 32x64 = 2 m-tiles(16) x 8 n-tiles(8), mma m16n8k8 tf32.
// ===========================================================================
__global__ void __launch_bounds__(256, 2)
gemm_tanh_mma(const float* __restrict__ A,      // inputs T x H (f32)
              const float* __restrict__ V) {    // H
    __shared__ float As[TILE_M * AS_STRIDE];     //  9216 B
    __shared__ float Bs[H * AS_STRIDE];          // 36864 B
    __shared__ float red[4][TILE_M];             //  1024 B

    const int tid = threadIdx.x;
    const int wid = tid >> 5;
    const int lane = tid & 31;
    const int g = lane >> 2;          // group id (0..7)
    const int t = lane & 3;           // thread-in-group (0..3)
    const int rg = wid >> 2;          // row group (0..1): rows rg*32 ..
    const int wc = wid & 3;           // col group (0..3): cols wc*64 ..
    const int row0 = blockIdx.x * TILE_M;

    float acc[2][8][4];               // [m-tile][n-tile][reg]
#pragma unroll
    for (int mt = 0; mt < 2; ++mt)
#pragma unroll
        for (int nt = 0; nt < 8; ++nt)
#pragma unroll
            for (int r = 0; r < 4; ++r) acc[mt][nt][r] = 0.f;

    for (int ch = 0; ch < NCH; ++ch) {
        const int k0 = ch * KT;
        // --- A chunk: 64x32 f32 = 512 float4, 2 per thread (convert to tf32) ---
#pragma unroll
        for (int i = 0; i < 2; ++i) {
            int idx = tid + i * 256;
            int r = idx >> 3;               // 8 float4 per row
            int c4 = idx & 7;
            int grow = row0 + r;
            float4 v = make_float4(0.f, 0.f, 0.f, 0.f);
            if (grow < T_CTX)
                v = *reinterpret_cast<const float4*>(&A[(size_t)grow * H + k0 + c4 * 4]);
            uint4 u = make_uint4(f2tf32(v.x), f2tf32(v.y), f2tf32(v.z), f2tf32(v.w));
            *reinterpret_cast<uint4*>(&As[r * AS_STRIDE + c4 * 4]) = u;
        }
        // --- B chunk: 256x32 (already tf32) = 2048 float4, 8 per thread ---
#pragma unroll
        for (int i = 0; i < 8; ++i) {
            int idx = tid + i * 256;
            int n = idx >> 3;
            int c4 = idx & 7;
            *reinterpret_cast<float4*>(&Bs[n * AS_STRIDE + c4 * 4]) =
                *reinterpret_cast<const float4*>(&g_WmT[(size_t)n * H + k0 + c4 * 4]);
        }
        __syncthreads();

#pragma unroll
        for (int ks = 0; ks < 4; ++ks) {
            const int k8 = ks * 8;
            uint32_t bf[8][2];
#pragma unroll
            for (int nt = 0; nt < 8; ++nt) {
                int bn = (wc * 64 + nt * 8 + g) * AS_STRIDE + k8;
                bf[nt][0] = __float_as_uint(Bs[bn + t]);
                bf[nt][1] = __float_as_uint(Bs[bn + t + 4]);
            }
            uint32_t af[2][4];
#pragma unroll
            for (int mt = 0; mt < 2; ++mt) {
                int ar = (rg * 32 + mt * 16 + g) * AS_STRIDE + k8;
                af[mt][0] = __float_as_uint(As[ar + t]);
                af[mt][1] = __float_as_uint(As[ar + 8 * AS_STRIDE + t]);
                af[mt][2] = __float_as_uint(As[ar + t + 4]);
                af[mt][3] = __float_as_uint(As[ar + 8 * AS_STRIDE + t + 4]);
            }
#pragma unroll
            for (int mt = 0; mt < 2; ++mt)
#pragma unroll
                for (int nt = 0; nt < 8; ++nt)
                    mma_tf32(acc[mt][nt], af[mt], bf[nt]);
        }
        __syncthreads();
    }

    // --- epilogue: tanh + V-dot, fused in registers ---
    // Thread owns rows {mt*16+g, mt*16+g+8} and cols {wc*64+nt*8+t*2, +1}.
    float p[4] = {0.f, 0.f, 0.f, 0.f};   // p[mt*2+h], h: row offset 0 / +8
#pragma unroll
    for (int nt = 0; nt < 8; ++nt) {
        int cn = wc * 64 + nt * 8 + t * 2;
        float v0 = V[cn],        v1 = V[cn + 1];
        float q0 = g_proj[cn],   q1 = g_proj[cn + 1];
#pragma unroll
        for (int mt = 0; mt < 2; ++mt) {
            p[mt * 2 + 0] = fmaf(tanh_fast(acc[mt][nt][0] + q0), v0,
                            fmaf(tanh_fast(acc[mt][nt][1] + q1), v1, p[mt * 2 + 0]));
            p[mt * 2 + 1] = fmaf(tanh_fast(acc[mt][nt][2] + q0), v0,
                            fmaf(tanh_fast(acc[mt][nt][3] + q1), v1, p[mt * 2 + 1]));
        }
    }
    // reduce over the 4 lanes of each group (fixed order -> deterministic)
#pragma unroll
    for (int j = 0; j < 4; ++j) {
        p[j] += __shfl_xor_sync(0xffffffffu, p[j], 1);
        p[j] += __shfl_xor_sync(0xffffffffu, p[j], 2);
    }
    if (t == 0) {
#pragma unroll
        for (int mt = 0; mt < 2; ++mt)
#pragma unroll
            for (int h = 0; h < 2; ++h)
                red[wc][rg * 32 + mt * 16 + h * 8 + g] = p[mt * 2 + h];
    }
    __syncthreads();
    if (tid < TILE_M) {
        float s = ((red[0][tid] + red[1][tid]) + (red[2][tid] + red[3][tid]));
        int grow = row0 + tid;
        if (grow < T_CTX) g_At[grow] = s;
    }
}

// ===========================================================================
// Two-stage logsumexp over At
// ===========================================================================
__global__ void softmax_part_kernel() {
    __shared__ float sm[1024];
    const int tid = threadIdx.x;
    const int base = blockIdx.x * 4096 + tid;

    float v[4], m = -1e30f;
#pragma unroll
    for (int j = 0; j < 4; ++j) {
        int tt = base + j * 1024;
        v[j] = (tt < T_CTX) ? g_At[tt] : -1e30f;
        m = fmaxf(m, v[j]);
    }
    sm[tid] = m;
    __syncthreads();
    for (int s = 512; s > 0; s >>= 1) {
        if (tid < s) sm[tid] = fmaxf(sm[tid], sm[tid + s]);
        __syncthreads();
    }
    const float bm = sm[0];
    __syncthreads();

    float sum = 0.f;
#pragma unroll
    for (int j = 0; j < 4; ++j) sum += expf(v[j] - bm);
    sm[tid] = sum;
    __syncthreads();
    for (int s = 512; s > 0; s >>= 1) {
        if (tid < s) sm[tid] += sm[tid + s];
        __syncthreads();
    }
    if (tid == 0) { g_sm_m[blockIdx.x] = bm; g_sm_s[blockIdx.x] = sm[0]; }
}

__global__ void softmax_final_kernel() {
    if (threadIdx.x == 0) {
        float M = -1e30f;
        for (int i = 0; i < SM_BLOCKS; ++i) M = fmaxf(M, g_sm_m[i]);
        float S = 0.f;
        for (int i = 0; i < SM_BLOCKS; ++i) S += g_sm_s[i] * expf(g_sm_m[i] - M);
        g_lse = M + logf(S);
    }
}

// ===========================================================================
// alphat out + per-block ct partials
// ===========================================================================
__global__ void __launch_bounds__(256)
ct_kernel(const float* __restrict__ A, float* __restrict__ out_alpha) {
    const int b = blockIdx.x;
    const int t0 = b * E_CHUNK;
    const int tid = threadIdx.x;
    const float lse = g_lse;
    const int tend = min(t0 + E_CHUNK, T_CTX);

    if (tid < E_CHUNK && t0 + tid < tend)
        out_alpha[t0 + tid] = g_At[t0 + tid] - lse;

    float a0 = 0.f, a1 = 0.f, a2 = 0.f, a3 = 0.f, a4 = 0.f, a5 = 0.f, a6 = 0.f, a7 = 0.f;
    int t = t0;
    for (; t + 8 <= tend; t += 8) {
        a0 = fmaf(g_At[t]     - lse, A[(size_t)(t)     * H + tid], a0);
        a1 = fmaf(g_At[t + 1] - lse, A[(size_t)(t + 1) * H + tid], a1);
        a2 = fmaf(g_At[t + 2] - lse, A[(size_t)(t + 2) * H + tid], a2);
        a3 = fmaf(g_At[t + 3] - lse, A[(size_t)(t + 3) * H + tid], a3);
        a4 = fmaf(g_At[t + 4] - lse, A[(size_t)(t + 4) * H + tid], a4);
        a5 = fmaf(g_At[t + 5] - lse, A[(size_t)(t + 5) * H + tid], a5);
        a6 = fmaf(g_At[t + 6] - lse, A[(size_t)(t + 6) * H + tid], a6);
        a7 = fmaf(g_At[t + 7] - lse, A[(size_t)(t + 7) * H + tid], a7);
    }
    for (; t < tend; ++t)
        a0 = fmaf(g_At[t] - lse, A[(size_t)t * H + tid], a0);

    g_ct_partial[b][tid] = (((a0 + a1) + (a2 + a3)) + ((a4 + a5) + (a6 + a7)));
}

__global__ void ct_final_kernel(float* __restrict__ out_ct) {
    const int h = threadIdx.x;
    float s0 = 0.f, s1 = 0.f;
#pragma unroll 4
    for (int b = 0; b < NB_E; b += 2) {       // NB_E = 782 (even), fixed order
        s0 += g_ct_partial[b][h];
        s1 += g_ct_partial[b + 1][h];
    }
    out_ct[h] = s0 + s1;
}

// ===========================================================================
extern "C" void kernel_launch(void* const* d_in, const int* in_sizes, int n_in,
                              void* d_out, int out_size) {
    const float* inputs = (const float*)d_in[0];   // (T, H)
    const float* hc     = (const float*)d_in[1];   // (1, H)
    const float* Wm     = (const float*)d_in[2];   // (H, H)
    const float* V      = (const float*)d_in[3];   // (H, 1)
    const float* W1     = (const float*)d_in[4];   // (H, H)
    float* out = (float*)d_out;                    // [alphat (T) | ct (H)]

    proj_kernel<<<1, 256>>>(hc, W1);
    transpose_kernel<<<64, dim3(32, 8)>>>(Wm);
    gemm_tanh_mma<<<NB_G, 256>>>(inputs, V);
    softmax_part_kernel<<<SM_BLOCKS, 1024>>>();
    softmax_final_kernel<<<1, 32>>>();
    ct_kernel<<<NB_E, 256>>>(inputs, out);
    ct_final_kernel<<<1, 256>>>(out + T_CTX);
}

// round 4
// speedup vs baseline: 5.2820x; 1.1970x over previous
#include <cuda_runtime.h>
#include <math.h>
#include <stdint.h>

#define T_CTX 100000
#define H 256

// ---- GEMM tiling (warp mma.sync tf32, cp.async double-buffered) ----
#define TILE_M 64                                // rows per CTA
#define NB_G ((T_CTX + TILE_M - 1) / TILE_M)     // 1563
#define KT 32                                    // K chunk
#define NCH (H / KT)                             // 8
#define AS_STRIDE 36                             // padded: conflict-free frags
#define ABUF (TILE_M * AS_STRIDE)                // floats per A buffer
#define BBUF (H * AS_STRIDE)                     // floats per B buffer
#define SMEM_GEMM ((2 * ABUF + 2 * BBUF + 4 * TILE_M) * 4)   // 93184 B

// ---- softmax / ct ----
#define SM_BLOCKS 25
#define E_CHUNK 128
#define NB_E ((T_CTX + E_CHUNK - 1) / E_CHUNK)   // 782
#define CTF1 8                                   // ct_final stage-1 blocks

// Scratch (static device globals: allocation-free per harness rules)
__device__ float g_At[T_CTX];
__device__ float g_proj[H];
__device__ float g_WmT[H * H];                   // transposed + tf32(rna)
__device__ float g_lse;
__device__ float g_sm_m[SM_BLOCKS];
__device__ float g_sm_s[SM_BLOCKS];
__device__ float g_ct_partial[NB_E][H];
__device__ float g_ct_partial2[CTF1][H];

// ===========================================================================
// helpers
// ===========================================================================
__device__ __forceinline__ float tanh_fast(float x) {
    float y;
    asm("tanh.approx.f32 %0, %1;" : "=f"(y) : "f"(x));
    return y;
}
__device__ __forceinline__ uint32_t f2tf32(float x) {
    uint32_t r;
    asm("cvt.rna.tf32.f32 %0, %1;" : "=r"(r) : "f"(x));
    return r;
}
__device__ __forceinline__ uint32_t smem_u32(const void* p) {
    uint32_t a;
    asm("{ .reg .u64 t; cvta.to.shared.u64 t, %1; cvt.u32.u64 %0, t; }" : "=r"(a) : "l"(p));
    return a;
}
__device__ __forceinline__ void cp16(uint32_t dst, const void* src) {
    asm volatile("cp.async.cg.shared.global [%0], [%1], 16;" :: "r"(dst), "l"(src) : "memory");
}
__device__ __forceinline__ void cp16z(uint32_t dst, const void* src, int sz) {
    asm volatile("cp.async.cg.shared.global [%0], [%1], 16, %2;"
                 :: "r"(dst), "l"(src), "r"(sz) : "memory");
}
__device__ __forceinline__ void cp_commit() {
    asm volatile("cp.async.commit_group;" ::: "memory");
}
__device__ __forceinline__ void mma_tf32(float d[4], const uint32_t a[4], const uint32_t b[2]) {
    asm volatile(
        "mma.sync.aligned.m16n8k8.row.col.f32.tf32.tf32.f32 "
        "{%0,%1,%2,%3}, {%4,%5,%6,%7}, {%8,%9}, {%0,%1,%2,%3};"
        : "+f"(d[0]), "+f"(d[1]), "+f"(d[2]), "+f"(d[3])
        : "r"(a[0]), "r"(a[1]), "r"(a[2]), "r"(a[3]), "r"(b[0]), "r"(b[1]));
}

// ===========================================================================
// proj = hc @ W1^T  (tiny)
// ===========================================================================
__global__ void proj_kernel(const float* __restrict__ hc, const float* __restrict__ W1) {
    int j = threadIdx.x;
    float s = 0.f;
#pragma unroll 8
    for (int k = 0; k < H; ++k) s = fmaf(hc[k], W1[j * H + k], s);
    g_proj[j] = s;
}

// ===========================================================================
// WmT[n][k] = tf32(Wm[k][n])
// ===========================================================================
__global__ void transpose_kernel(const float* __restrict__ Wm) {
    __shared__ float t[32][33];
    int bx = blockIdx.x & 7, by = blockIdx.x >> 3;
    int x = bx * 32 + threadIdx.x;
#pragma unroll
    for (int j = 0; j < 4; ++j) {
        int y = by * 32 + threadIdx.y + j * 8;
        t[threadIdx.y + j * 8][threadIdx.x] = Wm[y * H + x];
    }
    __syncthreads();
    int x2 = by * 32 + threadIdx.x;
#pragma unroll
    for (int j = 0; j < 4; ++j) {
        int y2 = bx * 32 + threadIdx.y + j * 8;
        g_WmT[y2 * H + x2] = __uint_as_float(f2tf32(t[threadIdx.x][threadIdx.y + j * 8]));
    }
}

// ===========================================================================
// Fused warp-MMA GEMM: At = tanh(inputs @ Wm + proj) @ V
// CTA 64x256xK256, 8 warps (2 row-groups x 4 col-groups), warp tile 32x64.
// cp.async double-buffered over 8 K-chunks of 32.
// ===========================================================================
__global__ void __launch_bounds__(256, 2)
gemm_tanh_mma(const float* __restrict__ A,      // inputs T x H (f32)
              const float* __restrict__ V) {    // H
    extern __shared__ float smp[];
    float* As  = smp;                            // [2][ABUF]
    float* Bs  = smp + 2 * ABUF;                 // [2][BBUF]
    float* red = smp + 2 * ABUF + 2 * BBUF;      // [4][TILE_M]
    const uint32_t as_u = smem_u32(As);
    const uint32_t bs_u = smem_u32(Bs);

    const int tid = threadIdx.x;
    const int wid = tid >> 5;
    const int lane = tid & 31;
    const int g = lane >> 2;          // group id (0..7)
    const int t = lane & 3;           // thread-in-group (0..3)
    const int rg = wid >> 2;          // row group (0..1)
    const int wc = wid & 3;           // col group (0..3)
    const int row0 = blockIdx.x * TILE_M;

    // per-thread load coords (2 A float4s, 8 B float4s per chunk)
    const int ar = tid >> 3;                  // A row for i=0 (0..31); i=1 adds 32
    const int ac4 = (tid & 7) * 4;            // float offset within chunk

    float acc[2][8][4];
#pragma unroll
    for (int mt = 0; mt < 2; ++mt)
#pragma unroll
        for (int nt = 0; nt < 8; ++nt)
#pragma unroll
            for (int r = 0; r < 4; ++r) acc[mt][nt][r] = 0.f;

    // ---- async load of chunk ch into buffer buf ----
    auto issue = [&](int ch, int buf) {
        const int k0 = ch * KT;
        const float* abase = A + (size_t)k0 + ac4;
#pragma unroll
        for (int i = 0; i < 2; ++i) {
            int r = ar + i * 32;
            int grow = row0 + r;
            int safe = grow < T_CTX ? grow : 0;
            cp16z(as_u + (buf * ABUF + r * AS_STRIDE + ac4) * 4,
                  abase + (size_t)safe * H, grow < T_CTX ? 16 : 0);
        }
        const float* bbase = g_WmT + k0 + ac4;
#pragma unroll
        for (int i = 0; i < 8; ++i) {
            int n = ar + i * 32;
            cp16(bs_u + (buf * BBUF + n * AS_STRIDE + ac4) * 4,
                 bbase + (size_t)n * H);
        }
        cp_commit();
    };

    issue(0, 0);

    for (int ch = 0; ch < NCH; ++ch) {
        const int buf = ch & 1;
        if (ch + 1 < NCH) {
            issue(ch + 1, buf ^ 1);
            asm volatile("cp.async.wait_group 1;" ::: "memory");
        } else {
            asm volatile("cp.async.wait_group 0;" ::: "memory");
        }
        __syncthreads();

        const float* Ab = As + buf * ABUF;
        const float* Bb = Bs + buf * BBUF;
#pragma unroll
        for (int ks = 0; ks < 4; ++ks) {
            const int k8 = ks * 8;
            uint32_t bf[8][2];
#pragma unroll
            for (int nt = 0; nt < 8; ++nt) {
                int bn = (wc * 64 + nt * 8 + g) * AS_STRIDE + k8;
                bf[nt][0] = __float_as_uint(Bb[bn + t]);
                bf[nt][1] = __float_as_uint(Bb[bn + t + 4]);
            }
            uint32_t af[2][4];
#pragma unroll
            for (int mt = 0; mt < 2; ++mt) {
                int arx = (rg * 32 + mt * 16 + g) * AS_STRIDE + k8;
                af[mt][0] = __float_as_uint(Ab[arx + t]);
                af[mt][1] = __float_as_uint(Ab[arx + 8 * AS_STRIDE + t]);
                af[mt][2] = __float_as_uint(Ab[arx + t + 4]);
                af[mt][3] = __float_as_uint(Ab[arx + 8 * AS_STRIDE + t + 4]);
            }
#pragma unroll
            for (int mt = 0; mt < 2; ++mt)
#pragma unroll
                for (int nt = 0; nt < 8; ++nt)
                    mma_tf32(acc[mt][nt], af[mt], bf[nt]);
        }
        __syncthreads();
    }

    // --- epilogue: tanh + V-dot in registers ---
    float p[4] = {0.f, 0.f, 0.f, 0.f};
#pragma unroll
    for (int nt = 0; nt < 8; ++nt) {
        int cn = wc * 64 + nt * 8 + t * 2;
        float v0 = V[cn],      v1 = V[cn + 1];
        float q0 = g_proj[cn], q1 = g_proj[cn + 1];
#pragma unroll
        for (int mt = 0; mt < 2; ++mt) {
            p[mt * 2 + 0] = fmaf(tanh_fast(acc[mt][nt][0] + q0), v0,
                            fmaf(tanh_fast(acc[mt][nt][1] + q1), v1, p[mt * 2 + 0]));
            p[mt * 2 + 1] = fmaf(tanh_fast(acc[mt][nt][2] + q0), v0,
                            fmaf(tanh_fast(acc[mt][nt][3] + q1), v1, p[mt * 2 + 1]));
        }
    }
#pragma unroll
    for (int j = 0; j < 4; ++j) {
        p[j] += __shfl_xor_sync(0xffffffffu, p[j], 1);
        p[j] += __shfl_xor_sync(0xffffffffu, p[j], 2);
    }
    if (t == 0) {
#pragma unroll
        for (int mt = 0; mt < 2; ++mt)
#pragma unroll
            for (int h = 0; h < 2; ++h)
                red[wc * TILE_M + rg * 32 + mt * 16 + h * 8 + g] = p[mt * 2 + h];
    }
    __syncthreads();
    if (tid < TILE_M) {
        float s = ((red[tid] + red[TILE_M + tid]) +
                   (red[2 * TILE_M + tid] + red[3 * TILE_M + tid]));
        int grow = row0 + tid;
        if (grow < T_CTX) g_At[grow] = s;
    }
}

// ===========================================================================
// Two-stage logsumexp over At (warp-shuffle reduces)
// ===========================================================================
__global__ void softmax_part_kernel() {
    __shared__ float wred[32];
    const int tid = threadIdx.x;
    const int lane = tid & 31;
    const int wid = tid >> 5;
    const int base = blockIdx.x * 4096 + tid;

    float v[4], m = -1e30f;
#pragma unroll
    for (int j = 0; j < 4; ++j) {
        int tt = base + j * 1024;
        v[j] = (tt < T_CTX) ? g_At[tt] : -1e30f;
        m = fmaxf(m, v[j]);
    }
#pragma unroll
    for (int s = 16; s > 0; s >>= 1) m = fmaxf(m, __shfl_xor_sync(~0u, m, s));
    if (lane == 0) wred[wid] = m;
    __syncthreads();
    if (wid == 0) {
        float mm = wred[lane];
#pragma unroll
        for (int s = 16; s > 0; s >>= 1) mm = fmaxf(mm, __shfl_xor_sync(~0u, mm, s));
        wred[lane] = mm;                 // all lanes hold block max -> wred[0..31]
    }
    __syncthreads();
    const float bm = wred[0];

    float sum = 0.f;
#pragma unroll
    for (int j = 0; j < 4; ++j) sum += expf(v[j] - bm);
#pragma unroll
    for (int s = 16; s > 0; s >>= 1) sum += __shfl_xor_sync(~0u, sum, s);
    __syncthreads();                     // reuse wred safely
    if (lane == 0) wred[wid] = sum;
    __syncthreads();
    if (tid == 0) {
        float S = 0.f;
#pragma unroll
        for (int i = 0; i < 32; ++i) S += wred[i];   // fixed order
        g_sm_m[blockIdx.x] = bm;
        g_sm_s[blockIdx.x] = S;
    }
}

__global__ void softmax_final_kernel() {
    const int lane = threadIdx.x;        // 32
    float m = -1e30f;
    for (int i = lane; i < SM_BLOCKS; i += 32) m = fmaxf(m, g_sm_m[i]);
#pragma unroll
    for (int s = 16; s > 0; s >>= 1) m = fmaxf(m, __shfl_xor_sync(~0u, m, s));
    float S = 0.f;
    for (int i = lane; i < SM_BLOCKS; i += 32) S += g_sm_s[i] * expf(g_sm_m[i] - m);
#pragma unroll
    for (int s = 16; s > 0; s >>= 1) S += __shfl_xor_sync(~0u, S, s);
    if (lane == 0) g_lse = m + logf(S);
}

// ===========================================================================
// alphat out + per-block ct partials
// ===========================================================================
__global__ void __launch_bounds__(256)
ct_kernel(const float* __restrict__ A, float* __restrict__ out_alpha) {
    const int b = blockIdx.x;
    const int t0 = b * E_CHUNK;
    const int tid = threadIdx.x;
    const float lse = g_lse;
    const int tend = min(t0 + E_CHUNK, T_CTX);

    if (tid < E_CHUNK && t0 + tid < tend)
        out_alpha[t0 + tid] = g_At[t0 + tid] - lse;

    float a0 = 0.f, a1 = 0.f, a2 = 0.f, a3 = 0.f, a4 = 0.f, a5 = 0.f, a6 = 0.f, a7 = 0.f;
    int t = t0;
    for (; t + 8 <= tend; t += 8) {
        a0 = fmaf(g_At[t]     - lse, A[(size_t)(t)     * H + tid], a0);
        a1 = fmaf(g_At[t + 1] - lse, A[(size_t)(t + 1) * H + tid], a1);
        a2 = fmaf(g_At[t + 2] - lse, A[(size_t)(t + 2) * H + tid], a2);
        a3 = fmaf(g_At[t + 3] - lse, A[(size_t)(t + 3) * H + tid], a3);
        a4 = fmaf(g_At[t + 4] - lse, A[(size_t)(t + 4) * H + tid], a4);
        a5 = fmaf(g_At[t + 5] - lse, A[(size_t)(t + 5) * H + tid], a5);
        a6 = fmaf(g_At[t + 6] - lse, A[(size_t)(t + 6) * H + tid], a6);
        a7 = fmaf(g_At[t + 7] - lse, A[(size_t)(t + 7) * H + tid], a7);
    }
    for (; t < tend; ++t)
        a0 = fmaf(g_At[t] - lse, A[(size_t)t * H + tid], a0);

    g_ct_partial[b][tid] = (((a0 + a1) + (a2 + a3)) + ((a4 + a5) + (a6 + a7)));
}

__global__ void ct_final1_kernel() {
    const int j = blockIdx.x;            // 0..CTF1-1
    const int h = threadIdx.x;           // 256
    float s = 0.f;
    for (int b = j; b < NB_E; b += CTF1) s += g_ct_partial[b][h];  // fixed order
    g_ct_partial2[j][h] = s;
}

__global__ void ct_final2_kernel(float* __restrict__ out_ct) {
    const int h = threadIdx.x;
    float s = 0.f;
#pragma unroll
    for (int j = 0; j < CTF1; ++j) s += g_ct_partial2[j][h];       // fixed order
    out_ct[h] = s;
}

// ===========================================================================
extern "C" void kernel_launch(void* const* d_in, const int* in_sizes, int n_in,
                              void* d_out, int out_size) {
    const float* inputs = (const float*)d_in[0];   // (T, H)
    const float* hc     = (const float*)d_in[1];   // (1, H)
    const float* Wm     = (const float*)d_in[2];   // (H, H)
    const float* V      = (const float*)d_in[3];   // (H, 1)
    const float* W1     = (const float*)d_in[4];   // (H, H)
    float* out = (float*)d_out;                    // [alphat (T) | ct (H)]

    static int smem_set = 0;
    if (!smem_set) {
        cudaFuncSetAttribute(gemm_tanh_mma,
                             cudaFuncAttributeMaxDynamicSharedMemorySize, SMEM_GEMM);
        smem_set = 1;
    }

    proj_kernel<<<1, 256>>>(hc, W1);
    transpose_kernel<<<64, dim3(32, 8)>>>(Wm);
    gemm_tanh_mma<<<NB_G, 256, SMEM_GEMM>>>(inputs, V);
    softmax_part_kernel<<<SM_BLOCKS, 1024>>>();
    softmax_final_kernel<<<1, 32>>>();
    ct_kernel<<<NB_E, 256>>>(inputs, out);
    ct_final1_kernel<<<CTF1, 256>>>();
    ct_final2_kernel<<<1, 256>>>(out + T_CTX);
}

// round 5
// speedup vs baseline: 6.4929x; 1.2292x over previous
#include <cuda_runtime.h>
#include <cuda_fp16.h>
#include <math.h>
#include <stdint.h>

#define T_CTX 100000
#define H 256

// ---- GEMM tiling (warp mma.sync f16 m16n8k16, cp.async + reg prefetch) ----
#define TILE_M 64                                // rows per CTA
#define NB_G ((T_CTX + TILE_M - 1) / TILE_M)     // 1563
#define KT 64                                    // K chunk (elements)
#define NCH (H / KT)                             // 4
#define ASTR 72                                  // fp16 row stride: conflict-free frags
#define ABUF_H (TILE_M * ASTR)                   // halves per A buffer
#define BBUF_H (H * ASTR)                        // halves per B buffer
#define SMEM_GEMM ((2 * ABUF_H + 2 * BBUF_H) * 2 + 4 * TILE_M * 4)   // 93184 B

// ---- softmax / ct ----
#define SM_BLOCKS 25
#define E_CHUNK 128
#define NB_E ((T_CTX + E_CHUNK - 1) / E_CHUNK)   // 782
#define CTF1 8

// Scratch (static device globals: allocation-free per harness rules)
__device__ float g_At[T_CTX];
__device__ float g_proj[H];
__device__ __half g_WmTh[H * H];                 // Wm transposed, fp16(rn)
__device__ float g_lse;
__device__ float g_sm_m[SM_BLOCKS];
__device__ float g_sm_s[SM_BLOCKS];
__device__ float g_ct_partial[NB_E][H];
__device__ float g_ct_partial2[CTF1][H];

// ===========================================================================
// helpers
// ===========================================================================
__device__ __forceinline__ float tanh_fast(float x) {
    float y;
    asm("tanh.approx.f32 %0, %1;" : "=f"(y) : "f"(x));
    return y;
}
__device__ __forceinline__ uint32_t smem_u32(const void* p) {
    uint32_t a;
    asm("{ .reg .u64 t; cvta.to.shared.u64 t, %1; cvt.u32.u64 %0, t; }" : "=r"(a) : "l"(p));
    return a;
}
__device__ __forceinline__ void cp16(uint32_t dst, const void* src) {
    asm volatile("cp.async.cg.shared.global [%0], [%1], 16;" :: "r"(dst), "l"(src) : "memory");
}
__device__ __forceinline__ void cp_commit() {
    asm volatile("cp.async.commit_group;" ::: "memory");
}
__device__ __forceinline__ void mma_f16(float d[4], const uint32_t a[4], const uint32_t b[2]) {
    asm volatile(
        "mma.sync.aligned.m16n8k16.row.col.f32.f16.f16.f32 "
        "{%0,%1,%2,%3}, {%4,%5,%6,%7}, {%8,%9}, {%0,%1,%2,%3};"
        : "+f"(d[0]), "+f"(d[1]), "+f"(d[2]), "+f"(d[3])
        : "r"(a[0]), "r"(a[1]), "r"(a[2]), "r"(a[3]), "r"(b[0]), "r"(b[1]));
}

// ===========================================================================
// proj = hc @ W1^T  (tiny)
// ===========================================================================
__global__ void proj_kernel(const float* __restrict__ hc, const float* __restrict__ W1) {
    int j = threadIdx.x;
    float s = 0.f;
#pragma unroll 8
    for (int k = 0; k < H; ++k) s = fmaf(hc[k], W1[j * H + k], s);
    g_proj[j] = s;
}

// ===========================================================================
// WmTh[n][k] = f16(Wm[k][n])
// ===========================================================================
__global__ void transpose_kernel(const float* __restrict__ Wm) {
    __shared__ float t[32][33];
    int bx = blockIdx.x & 7, by = blockIdx.x >> 3;
    int x = bx * 32 + threadIdx.x;
#pragma unroll
    for (int j = 0; j < 4; ++j) {
        int y = by * 32 + threadIdx.y + j * 8;
        t[threadIdx.y + j * 8][threadIdx.x] = Wm[y * H + x];
    }
    __syncthreads();
    int x2 = by * 32 + threadIdx.x;
#pragma unroll
    for (int j = 0; j < 4; ++j) {
        int y2 = bx * 32 + threadIdx.y + j * 8;
        g_WmTh[y2 * H + x2] = __float2half_rn(t[threadIdx.x][threadIdx.y + j * 8]);
    }
}

// ===========================================================================
// Fused warp-MMA GEMM (fp16 k16): At = tanh(inputs @ Wm + proj) @ V
// CTA 64x256xK256, 8 warps (2 row x 4 col groups), warp tile 32x64.
// B: cp.async double-buffered (fp16 global). A: LDG fp32 -> cvt -> STS fp16,
// register-prefetched one chunk ahead.
// ===========================================================================
__global__ void __launch_bounds__(256, 2)
gemm_tanh_mma(const float* __restrict__ A,      // inputs T x H (f32)
              const float* __restrict__ V) {    // H
    extern __shared__ __half smh[];
    __half* As = smh;                            // [2][TILE_M][ASTR]
    __half* Bs = smh + 2 * ABUF_H;               // [2][H][ASTR]
    float* red = (float*)(smh + 2 * ABUF_H + 2 * BBUF_H);  // [4][TILE_M]
    const uint32_t bs_u = smem_u32(Bs);

    const int tid = threadIdx.x;
    const int wid = tid >> 5;
    const int lane = tid & 31;
    const int g = lane >> 2;
    const int t = lane & 3;
    const int rg = wid >> 2;          // row group (0..1)
    const int wc = wid & 3;           // col group (0..3)
    const int row0 = blockIdx.x * TILE_M;

    // A load coords: per chunk 64x64 f32 = 1024 float4; 4/thread
    const int lar = 0;  (void)lar;
    float4 pa[4];

    float acc[2][8][4];
#pragma unroll
    for (int mt = 0; mt < 2; ++mt)
#pragma unroll
        for (int nt = 0; nt < 8; ++nt)
#pragma unroll
            for (int r = 0; r < 4; ++r) acc[mt][nt][r] = 0.f;

    auto ldgA = [&](int ch) {
        const int k0 = ch * KT;
#pragma unroll
        for (int i = 0; i < 4; ++i) {
            int idx = tid + i * 256;
            int r = idx >> 4;                 // 16 float4 per row
            int c = (idx & 15) * 4;
            int grow = row0 + r;
            pa[i] = (grow < T_CTX)
                ? *reinterpret_cast<const float4*>(&A[(size_t)grow * H + k0 + c])
                : make_float4(0.f, 0.f, 0.f, 0.f);
        }
    };
    auto stsA = [&](int buf) {
#pragma unroll
        for (int i = 0; i < 4; ++i) {
            int idx = tid + i * 256;
            int r = idx >> 4;
            int c = (idx & 15) * 4;
            __half2 h0 = __floats2half2_rn(pa[i].x, pa[i].y);
            __half2 h1 = __floats2half2_rn(pa[i].z, pa[i].w);
            *reinterpret_cast<__half2*>(&As[buf * ABUF_H + r * ASTR + c]) = h0;
            *reinterpret_cast<__half2*>(&As[buf * ABUF_H + r * ASTR + c + 2]) = h1;
        }
    };
    auto cpB = [&](int ch, int buf) {
        const int k0 = ch * KT;
#pragma unroll
        for (int i = 0; i < 8; ++i) {
            int idx = tid + i * 256;
            int n = idx >> 3;                 // 8 x 16B per row of 64 halves
            int c8 = (idx & 7) * 8;
            cp16(bs_u + (uint32_t)(buf * BBUF_H + n * ASTR + c8) * 2,
                 g_WmTh + (size_t)n * H + k0 + c8);
        }
        cp_commit();
    };

    auto compute = [&](int buf) {
#pragma unroll
        for (int ks = 0; ks < 4; ++ks) {
            const int koff = ks * 16;
            uint32_t bf[8][2];
#pragma unroll
            for (int nt = 0; nt < 8; ++nt) {
                int nb = buf * BBUF_H + (wc * 64 + nt * 8 + g) * ASTR + koff;
                bf[nt][0] = *reinterpret_cast<const uint32_t*>(&Bs[nb + 2 * t]);
                bf[nt][1] = *reinterpret_cast<const uint32_t*>(&Bs[nb + 8 + 2 * t]);
            }
#pragma unroll
            for (int mt = 0; mt < 2; ++mt) {
                int ab = buf * ABUF_H + (rg * 32 + mt * 16 + g) * ASTR + koff;
                uint32_t af[4];
                af[0] = *reinterpret_cast<const uint32_t*>(&As[ab + 2 * t]);
                af[1] = *reinterpret_cast<const uint32_t*>(&As[ab + 8 * ASTR + 2 * t]);
                af[2] = *reinterpret_cast<const uint32_t*>(&As[ab + 8 + 2 * t]);
                af[3] = *reinterpret_cast<const uint32_t*>(&As[ab + 8 * ASTR + 8 + 2 * t]);
#pragma unroll
                for (int nt = 0; nt < 8; ++nt)
                    mma_f16(acc[mt][nt], af, bf[nt]);
            }
        }
    };

    // ---- prologue ----
    ldgA(0); cpB(0, 0);
    stsA(0);
    ldgA(1); cpB(1, 1);
    asm volatile("cp.async.wait_group 1;" ::: "memory");   // B0 arrived
    __syncthreads();

    // ---- mainloop: 4 chunks ----
#pragma unroll
    for (int ch = 0; ch < NCH; ++ch) {
        const int buf = ch & 1;
        if (ch < NCH - 1) stsA(buf ^ 1);       // A(ch+1) -> other buffer (safe)
        if (ch < NCH - 2) ldgA(ch + 2);        // prefetch A(ch+2) to regs
        compute(buf);
        if (ch < NCH - 1) {
            __syncthreads();                   // all done reading buf
            if (ch < NCH - 2) cpB(ch + 2, buf);
            if (ch < NCH - 2)
                asm volatile("cp.async.wait_group 1;" ::: "memory");
            else
                asm volatile("cp.async.wait_group 0;" ::: "memory");
            __syncthreads();                   // B(ch+1) + A(ch+1) visible
        }
    }

    // --- epilogue: tanh + V-dot in registers (D layout same as k8) ---
    float p[4] = {0.f, 0.f, 0.f, 0.f};
#pragma unroll
    for (int nt = 0; nt < 8; ++nt) {
        int cn = wc * 64 + nt * 8 + t * 2;
        float v0 = V[cn],      v1 = V[cn + 1];
        float q0 = g_proj[cn], q1 = g_proj[cn + 1];
#pragma unroll
        for (int mt = 0; mt < 2; ++mt) {
            p[mt * 2 + 0] = fmaf(tanh_fast(acc[mt][nt][0] + q0), v0,
                            fmaf(tanh_fast(acc[mt][nt][1] + q1), v1, p[mt * 2 + 0]));
            p[mt * 2 + 1] = fmaf(tanh_fast(acc[mt][nt][2] + q0), v0,
                            fmaf(tanh_fast(acc[mt][nt][3] + q1), v1, p[mt * 2 + 1]));
        }
    }
#pragma unroll
    for (int j = 0; j < 4; ++j) {
        p[j] += __shfl_xor_sync(0xffffffffu, p[j], 1);
        p[j] += __shfl_xor_sync(0xffffffffu, p[j], 2);
    }
    if (t == 0) {
#pragma unroll
        for (int mt = 0; mt < 2; ++mt)
#pragma unroll
            for (int h = 0; h < 2; ++h)
                red[wc * TILE_M + rg * 32 + mt * 16 + h * 8 + g] = p[mt * 2 + h];
    }
    __syncthreads();
    if (tid < TILE_M) {
        float s = ((red[tid] + red[TILE_M + tid]) +
                   (red[2 * TILE_M + tid] + red[3 * TILE_M + tid]));
        int grow = row0 + tid;
        if (grow < T_CTX) g_At[grow] = s;
    }
}

// ===========================================================================
// Two-stage logsumexp over At (warp-shuffle reduces)
// ===========================================================================
__global__ void softmax_part_kernel() {
    __shared__ float wred[32];
    const int tid = threadIdx.x;
    const int lane = tid & 31;
    const int wid = tid >> 5;
    const int base = blockIdx.x * 4096 + tid;

    float v[4], m = -1e30f;
#pragma unroll
    for (int j = 0; j < 4; ++j) {
        int tt = base + j * 1024;
        v[j] = (tt < T_CTX) ? g_At[tt] : -1e30f;
        m = fmaxf(m, v[j]);
    }
#pragma unroll
    for (int s = 16; s > 0; s >>= 1) m = fmaxf(m, __shfl_xor_sync(~0u, m, s));
    if (lane == 0) wred[wid] = m;
    __syncthreads();
    if (wid == 0) {
        float mm = wred[lane];
#pragma unroll
        for (int s = 16; s > 0; s >>= 1) mm = fmaxf(mm, __shfl_xor_sync(~0u, mm, s));
        wred[lane] = mm;
    }
    __syncthreads();
    const float bm = wred[0];

    float sum = 0.f;
#pragma unroll
    for (int j = 0; j < 4; ++j) sum += expf(v[j] - bm);
#pragma unroll
    for (int s = 16; s > 0; s >>= 1) sum += __shfl_xor_sync(~0u, sum, s);
    __syncthreads();
    if (lane == 0) wred[wid] = sum;
    __syncthreads();
    if (tid == 0) {
        float S = 0.f;
#pragma unroll
        for (int i = 0; i < 32; ++i) S += wred[i];   // fixed order
        g_sm_m[blockIdx.x] = bm;
        g_sm_s[blockIdx.x] = S;
    }
}

__global__ void softmax_final_kernel() {
    const int lane = threadIdx.x;        // 32
    float m = -1e30f;
    for (int i = lane; i < SM_BLOCKS; i += 32) m = fmaxf(m, g_sm_m[i]);
#pragma unroll
    for (int s = 16; s > 0; s >>= 1) m = fmaxf(m, __shfl_xor_sync(~0u, m, s));
    float S = 0.f;
    for (int i = lane; i < SM_BLOCKS; i += 32) S += g_sm_s[i] * expf(g_sm_m[i] - m);
#pragma unroll
    for (int s = 16; s > 0; s >>= 1) S += __shfl_xor_sync(~0u, S, s);
    if (lane == 0) g_lse = m + logf(S);
}

// ===========================================================================
// alphat out + per-block ct partials
// ===========================================================================
__global__ void __launch_bounds__(256)
ct_kernel(const float* __restrict__ A, float* __restrict__ out_alpha) {
    const int b = blockIdx.x;
    const int t0 = b * E_CHUNK;
    const int tid = threadIdx.x;
    const float lse = g_lse;
    const int tend = min(t0 + E_CHUNK, T_CTX);

    if (tid < E_CHUNK && t0 + tid < tend)
        out_alpha[t0 + tid] = g_At[t0 + tid] - lse;

    float a0 = 0.f, a1 = 0.f, a2 = 0.f, a3 = 0.f, a4 = 0.f, a5 = 0.f, a6 = 0.f, a7 = 0.f;
    int t = t0;
    for (; t + 8 <= tend; t += 8) {
        a0 = fmaf(g_At[t]     - lse, A[(size_t)(t)     * H + tid], a0);
        a1 = fmaf(g_At[t + 1] - lse, A[(size_t)(t + 1) * H + tid], a1);
        a2 = fmaf(g_At[t + 2] - lse, A[(size_t)(t + 2) * H + tid], a2);
        a3 = fmaf(g_At[t + 3] - lse, A[(size_t)(t + 3) * H + tid], a3);
        a4 = fmaf(g_At[t + 4] - lse, A[(size_t)(t + 4) * H + tid], a4);
        a5 = fmaf(g_At[t + 5] - lse, A[(size_t)(t + 5) * H + tid], a5);
        a6 = fmaf(g_At[t + 6] - lse, A[(size_t)(t + 6) * H + tid], a6);
        a7 = fmaf(g_At[t + 7] - lse, A[(size_t)(t + 7) * H + tid], a7);
    }
    for (; t < tend; ++t)
        a0 = fmaf(g_At[t] - lse, A[(size_t)t * H + tid], a0);

    g_ct_partial[b][tid] = (((a0 + a1) + (a2 + a3)) + ((a4 + a5) + (a6 + a7)));
}

__global__ void ct_final1_kernel() {
    const int j = blockIdx.x;
    const int h = threadIdx.x;
    float s = 0.f;
    for (int b = j; b < NB_E; b += CTF1) s += g_ct_partial[b][h];  // fixed order
    g_ct_partial2[j][h] = s;
}

__global__ void ct_final2_kernel(float* __restrict__ out_ct) {
    const int h = threadIdx.x;
    float s = 0.f;
#pragma unroll
    for (int j = 0; j < CTF1; ++j) s += g_ct_partial2[j][h];       // fixed order
    out_ct[h] = s;
}

// ===========================================================================
extern "C" void kernel_launch(void* const* d_in, const int* in_sizes, int n_in,
                              void* d_out, int out_size) {
    const float* inputs = (const float*)d_in[0];   // (T, H)
    const float* hc     = (const float*)d_in[1];   // (1, H)
    const float* Wm     = (const float*)d_in[2];   // (H, H)
    const float* V      = (const float*)d_in[3];   // (H, 1)
    const float* W1     = (const float*)d_in[4];   // (H, H)
    float* out = (float*)d_out;                    // [alphat (T) | ct (H)]

    static int smem_set = 0;
    if (!smem_set) {
        cudaFuncSetAttribute(gemm_tanh_mma,
                             cudaFuncAttributeMaxDynamicSharedMemorySize, SMEM_GEMM);
        smem_set = 1;
    }

    proj_kernel<<<1, 256>>>(hc, W1);
    transpose_kernel<<<64, dim3(32, 8)>>>(Wm);
    gemm_tanh_mma<<<NB_G, 256, SMEM_GEMM>>>(inputs, V);
    softmax_part_kernel<<<SM_BLOCKS, 1024>>>();
    softmax_final_kernel<<<1, 32>>>();
    ct_kernel<<<NB_E, 256>>>(inputs, out);
    ct_final1_kernel<<<CTF1, 256>>>();
    ct_final2_kernel<<<1, 256>>>(out + T_CTX);
}

// round 6
// speedup vs baseline: 7.6487x; 1.1780x over previous
#include <cuda_runtime.h>
#include <cuda_fp16.h>
#include <math.h>
#include <stdint.h>

#define T_CTX 100000
#define H 256

// ---- GEMM tiling (warp mma.sync f16 m16n8k16, ldmatrix, fused ct) ----
#define TILE_M 64                                // rows per CTA
#define NB_G ((T_CTX + TILE_M - 1) / TILE_M)     // 1563
#define KT 64                                    // K chunk (elements)
#define NCH (H / KT)                             // 4
#define ASTR 72                                  // fp16 row stride: conflict-free
#define ABUF_H (TILE_M * ASTR)                   // 4608 halves / chunk buffer
#define BBUF_H (H * ASTR)                        // 18432 halves / buffer
// 4 A chunk buffers (persistent) + 2 B buffers + red(256f) + at_s(64f)
#define SMEM_GEMM ((4 * ABUF_H + 2 * BBUF_H) * 2 + (4 * TILE_M + TILE_M) * 4) // 111872

// ---- softmax / ct reduce ----
#define SM_BLOCKS 98
#define CTR1 16

// Scratch (static device globals: allocation-free per harness rules)
__device__ float g_At[T_CTX];
__device__ float g_proj[H];
__device__ __half g_WmTh[H * H];                 // Wm transposed, fp16(rn)
__device__ float g_lse;
__device__ float g_sm_m[SM_BLOCKS];
__device__ float g_sm_s[SM_BLOCKS];
__device__ float g_ct1[NB_G][H];                 // per-CTA  Σ At[t]·M[t,h]
__device__ float g_cs1[NB_G][H];                 // per-CTA  Σ M[t,h]
__device__ float g_ct2[CTR1][H];
__device__ float g_cs2[CTR1][H];

// ===========================================================================
// helpers
// ===========================================================================
__device__ __forceinline__ float tanh_fast(float x) {
    float y;
    asm("tanh.approx.f32 %0, %1;" : "=f"(y) : "f"(x));
    return y;
}
__device__ __forceinline__ uint32_t smem_u32(const void* p) {
    uint32_t a;
    asm("{ .reg .u64 t; cvta.to.shared.u64 t, %1; cvt.u32.u64 %0, t; }" : "=r"(a) : "l"(p));
    return a;
}
__device__ __forceinline__ void cp16(uint32_t dst, const void* src) {
    asm volatile("cp.async.cg.shared.global [%0], [%1], 16;" :: "r"(dst), "l"(src) : "memory");
}
__device__ __forceinline__ void cp_commit() {
    asm volatile("cp.async.commit_group;" ::: "memory");
}
__device__ __forceinline__ void ldsm4(uint32_t& r0, uint32_t& r1, uint32_t& r2, uint32_t& r3,
                                      uint32_t addr) {
    asm volatile("ldmatrix.sync.aligned.m8n8.x4.shared.b16 {%0,%1,%2,%3}, [%4];"
                 : "=r"(r0), "=r"(r1), "=r"(r2), "=r"(r3) : "r"(addr));
}
__device__ __forceinline__ void mma_f16(float d[4], const uint32_t a[4], const uint32_t b[2]) {
    asm volatile(
        "mma.sync.aligned.m16n8k16.row.col.f32.f16.f16.f32 "
        "{%0,%1,%2,%3}, {%4,%5,%6,%7}, {%8,%9}, {%0,%1,%2,%3};"
        : "+f"(d[0]), "+f"(d[1]), "+f"(d[2]), "+f"(d[3])
        : "r"(a[0]), "r"(a[1]), "r"(a[2]), "r"(a[3]), "r"(b[0]), "r"(b[1]));
}

// ===========================================================================
// proj = hc @ W1^T  (tiny)
// ===========================================================================
__global__ void proj_kernel(const float* __restrict__ hc, const float* __restrict__ W1) {
    int j = threadIdx.x;
    float s = 0.f;
#pragma unroll 8
    for (int k = 0; k < H; ++k) s = fmaf(hc[k], W1[j * H + k], s);
    g_proj[j] = s;
}

// ===========================================================================
// WmTh[n][k] = f16(Wm[k][n])
// ===========================================================================
__global__ void transpose_kernel(const float* __restrict__ Wm) {
    __shared__ float t[32][33];
    int bx = blockIdx.x & 7, by = blockIdx.x >> 3;
    int x = bx * 32 + threadIdx.x;
#pragma unroll
    for (int j = 0; j < 4; ++j) {
        int y = by * 32 + threadIdx.y + j * 8;
        t[threadIdx.y + j * 8][threadIdx.x] = Wm[y * H + x];
    }
    __syncthreads();
    int x2 = by * 32 + threadIdx.x;
#pragma unroll
    for (int j = 0; j < 4; ++j) {
        int y2 = bx * 32 + threadIdx.y + j * 8;
        g_WmTh[y2 * H + x2] = __float2half_rn(t[threadIdx.x][threadIdx.y + j * 8]);
    }
}

// ===========================================================================
// Fused GEMM + tanh + V-dot + ct partials.
// CTA 64x256xK256, 8 warps (2 row x 4 col groups), warp tile 32x64.
// A: LDG f32 -> cvt f16 -> STS into 4 persistent chunk buffers.
// B: cp.async double-buffered. Fragments via ldmatrix.x4.
// Epilogue 2: ct1[c] = Σ_r At[r]·A[r][c], cs1[c] = Σ_r A[r][c] (fp16 M).
// ===========================================================================
__global__ void __launch_bounds__(256, 2)
gemm_tanh_mma(const float* __restrict__ A,      // inputs T x H (f32)
              const float* __restrict__ V) {    // H
    extern __shared__ __half smh[];
    __half* As = smh;                            // [4][TILE_M][ASTR]
    __half* Bs = smh + 4 * ABUF_H;               // [2][H][ASTR]
    float* red = (float*)(smh + 4 * ABUF_H + 2 * BBUF_H);  // [4][TILE_M]
    float* at_s = red + 4 * TILE_M;              // [TILE_M]
    const uint32_t as_u = smem_u32(As);
    const uint32_t bs_u = smem_u32(Bs);

    const int tid = threadIdx.x;
    const int wid = tid >> 5;
    const int lane = tid & 31;
    const int g = lane >> 2;
    const int t = lane & 3;
    const int rg = wid >> 2;          // row group (0..1)
    const int wc = wid & 3;           // col group (0..3)
    const int row0 = blockIdx.x * TILE_M;

    // ldmatrix lane-address bases (bytes), koff=0, buffer 0
    uint32_t a_lm[2], b_lm[4];
#pragma unroll
    for (int mt = 0; mt < 2; ++mt)
        a_lm[mt] = as_u + 2u * ((uint32_t)(rg * 32 + mt * 16 + (lane & 7) +
                                ((lane >> 3) & 1) * 8) * ASTR + ((lane >> 4) & 1) * 8);
#pragma unroll
    for (int np = 0; np < 4; ++np)
        b_lm[np] = bs_u + 2u * ((uint32_t)(wc * 64 + np * 16 + (lane & 7) +
                                ((lane >> 4) & 1) * 8) * ASTR + ((lane >> 3) & 1) * 8);

    float4 pa[4];
    float acc[2][8][4];
#pragma unroll
    for (int mt = 0; mt < 2; ++mt)
#pragma unroll
        for (int nt = 0; nt < 8; ++nt)
#pragma unroll
            for (int r = 0; r < 4; ++r) acc[mt][nt][r] = 0.f;

    auto ldgA = [&](int ch) {
        const int k0 = ch * KT;
#pragma unroll
        for (int i = 0; i < 4; ++i) {
            int idx = tid + i * 256;
            int r = idx >> 4;
            int c = (idx & 15) * 4;
            int grow = row0 + r;
            pa[i] = (grow < T_CTX)
                ? *reinterpret_cast<const float4*>(&A[(size_t)grow * H + k0 + c])
                : make_float4(0.f, 0.f, 0.f, 0.f);
        }
    };
    auto stsA = [&](int buf) {
#pragma unroll
        for (int i = 0; i < 4; ++i) {
            int idx = tid + i * 256;
            int r = idx >> 4;
            int c = (idx & 15) * 4;
            *reinterpret_cast<__half2*>(&As[buf * ABUF_H + r * ASTR + c]) =
                __floats2half2_rn(pa[i].x, pa[i].y);
            *reinterpret_cast<__half2*>(&As[buf * ABUF_H + r * ASTR + c + 2]) =
                __floats2half2_rn(pa[i].z, pa[i].w);
        }
    };
    auto cpB = [&](int ch, int buf) {
        const int k0 = ch * KT;
#pragma unroll
        for (int i = 0; i < 8; ++i) {
            int idx = tid + i * 256;
            int n = idx >> 3;
            int c8 = (idx & 7) * 8;
            cp16(bs_u + (uint32_t)(buf * BBUF_H + n * ASTR + c8) * 2,
                 g_WmTh + (size_t)n * H + k0 + c8);
        }
        cp_commit();
    };

    auto compute = [&](int ch, int bbuf) {
        const uint32_t aoff = (uint32_t)ch * (ABUF_H * 2);
        const uint32_t boff = (uint32_t)bbuf * (BBUF_H * 2);
#pragma unroll
        for (int ks = 0; ks < 4; ++ks) {
            const uint32_t koff = ks * 32;       // 16 halves
            uint32_t bf[8][2];
#pragma unroll
            for (int np = 0; np < 4; ++np)
                ldsm4(bf[2 * np][0], bf[2 * np][1], bf[2 * np + 1][0], bf[2 * np + 1][1],
                      b_lm[np] + boff + koff);
#pragma unroll
            for (int mt = 0; mt < 2; ++mt) {
                uint32_t af[4];
                ldsm4(af[0], af[1], af[2], af[3], a_lm[mt] + aoff + koff);
#pragma unroll
                for (int nt = 0; nt < 8; ++nt)
                    mma_f16(acc[mt][nt], af, bf[nt]);
            }
        }
    };

    // ---- prologue ----
    ldgA(0); cpB(0, 0);
    stsA(0);
    ldgA(1); cpB(1, 1);
    asm volatile("cp.async.wait_group 1;" ::: "memory");   // B0 arrived
    __syncthreads();

    // ---- mainloop: 4 chunks; A buffer = ch, B buffer = ch&1 ----
#pragma unroll
    for (int ch = 0; ch < NCH; ++ch) {
        const int bbuf = ch & 1;
        if (ch < NCH - 1) stsA(ch + 1);
        if (ch < NCH - 2) ldgA(ch + 2);
        compute(ch, bbuf);
        if (ch < NCH - 1) {
            __syncthreads();                   // all done reading B(bbuf); A(ch+1) visible
            if (ch < NCH - 2) {
                cpB(ch + 2, bbuf);
                asm volatile("cp.async.wait_group 1;" ::: "memory");
            } else {
                asm volatile("cp.async.wait_group 0;" ::: "memory");
            }
            __syncthreads();
        }
    }

    // --- epilogue 1: tanh + V-dot ---
    float p[4] = {0.f, 0.f, 0.f, 0.f};
#pragma unroll
    for (int nt = 0; nt < 8; ++nt) {
        int cn = wc * 64 + nt * 8 + t * 2;
        float v0 = V[cn],      v1 = V[cn + 1];
        float q0 = g_proj[cn], q1 = g_proj[cn + 1];
#pragma unroll
        for (int mt = 0; mt < 2; ++mt) {
            p[mt * 2 + 0] = fmaf(tanh_fast(acc[mt][nt][0] + q0), v0,
                            fmaf(tanh_fast(acc[mt][nt][1] + q1), v1, p[mt * 2 + 0]));
            p[mt * 2 + 1] = fmaf(tanh_fast(acc[mt][nt][2] + q0), v0,
                            fmaf(tanh_fast(acc[mt][nt][3] + q1), v1, p[mt * 2 + 1]));
        }
    }
#pragma unroll
    for (int j = 0; j < 4; ++j) {
        p[j] += __shfl_xor_sync(0xffffffffu, p[j], 1);
        p[j] += __shfl_xor_sync(0xffffffffu, p[j], 2);
    }
    if (t == 0) {
#pragma unroll
        for (int mt = 0; mt < 2; ++mt)
#pragma unroll
            for (int h = 0; h < 2; ++h)
                red[wc * TILE_M + rg * 32 + mt * 16 + h * 8 + g] = p[mt * 2 + h];
    }
    __syncthreads();
    if (tid < TILE_M) {
        float s = ((red[tid] + red[TILE_M + tid]) +
                   (red[2 * TILE_M + tid] + red[3 * TILE_M + tid]));
        at_s[tid] = s;
        int grow = row0 + tid;
        if (grow < T_CTX) g_At[grow] = s;
    }
    __syncthreads();

    // --- epilogue 2: ct partials from resident fp16 A tiles ---
    // thread = column c; OOB rows have A==0 so they contribute nothing.
    {
        const int c = tid;
        const __half* col = As + (c >> 6) * ABUF_H + (c & 63);
        float s1 = 0.f, s2 = 0.f;
#pragma unroll 8
        for (int r = 0; r < TILE_M; ++r) {
            float f = __half2float(col[r * ASTR]);
            s1 = fmaf(at_s[r], f, s1);
            s2 += f;
        }
        g_ct1[blockIdx.x][c] = s1;
        g_cs1[blockIdx.x][c] = s2;
    }
}

// ===========================================================================
// Two-stage logsumexp over At
// ===========================================================================
__global__ void softmax_part_kernel() {
    __shared__ float wred[32];
    const int tid = threadIdx.x;
    const int lane = tid & 31;
    const int wid = tid >> 5;
    const int tt = blockIdx.x * 1024 + tid;

    float v = (tt < T_CTX) ? g_At[tt] : -1e30f;
    float m = v;
#pragma unroll
    for (int s = 16; s > 0; s >>= 1) m = fmaxf(m, __shfl_xor_sync(~0u, m, s));
    if (lane == 0) wred[wid] = m;
    __syncthreads();
    if (wid == 0) {
        float mm = wred[lane];
#pragma unroll
        for (int s = 16; s > 0; s >>= 1) mm = fmaxf(mm, __shfl_xor_sync(~0u, mm, s));
        wred[lane] = mm;
    }
    __syncthreads();
    const float bm = wred[0];

    float sum = expf(v - bm);
#pragma unroll
    for (int s = 16; s > 0; s >>= 1) sum += __shfl_xor_sync(~0u, sum, s);
    __syncthreads();
    if (lane == 0) wred[wid] = sum;
    __syncthreads();
    if (tid == 0) {
        float S = 0.f;
#pragma unroll
        for (int i = 0; i < 32; ++i) S += wred[i];   // fixed order
        g_sm_m[blockIdx.x] = bm;
        g_sm_s[blockIdx.x] = S;
    }
}

__global__ void softmax_final_kernel() {
    const int lane = threadIdx.x;        // 32
    float m = -1e30f;
    for (int i = lane; i < SM_BLOCKS; i += 32) m = fmaxf(m, g_sm_m[i]);
#pragma unroll
    for (int s = 16; s > 0; s >>= 1) m = fmaxf(m, __shfl_xor_sync(~0u, m, s));
    float S = 0.f;
    for (int i = lane; i < SM_BLOCKS; i += 32) S += g_sm_s[i] * expf(g_sm_m[i] - m);
#pragma unroll
    for (int s = 16; s > 0; s >>= 1) S += __shfl_xor_sync(~0u, S, s);
    if (lane == 0) g_lse = m + logf(S);
}

// ===========================================================================
// alphat = At - lse
// ===========================================================================
__global__ void alpha_kernel(float* __restrict__ out_alpha) {
    int t = blockIdx.x * 1024 + threadIdx.x;
    if (t < T_CTX) out_alpha[t] = g_At[t] - g_lse;
}

// ===========================================================================
// ct reduction: ct[c] = Σ ct1 − lse · Σ cs1   (fixed-order, deterministic)
// ===========================================================================
__global__ void ctred1_kernel() {
    const int j = blockIdx.x;            // 0..CTR1-1
    const int c = threadIdx.x;           // 256
    float s1 = 0.f, s2 = 0.f;
    for (int b = j; b < NB_G; b += CTR1) {
        s1 += g_ct1[b][c];
        s2 += g_cs1[b][c];
    }
    g_ct2[j][c] = s1;
    g_cs2[j][c] = s2;
}

__global__ void ctred2_kernel(float* __restrict__ out_ct) {
    const int c = threadIdx.x;
    float s1 = 0.f, s2 = 0.f;
#pragma unroll
    for (int j = 0; j < CTR1; ++j) {
        s1 += g_ct2[j][c];
        s2 += g_cs2[j][c];
    }
    out_ct[c] = s1 - g_lse * s2;
}

// ===========================================================================
extern "C" void kernel_launch(void* const* d_in, const int* in_sizes, int n_in,
                              void* d_out, int out_size) {
    const float* inputs = (const float*)d_in[0];   // (T, H)
    const float* hc     = (const float*)d_in[1];   // (1, H)
    const float* Wm     = (const float*)d_in[2];   // (H, H)
    const float* V      = (const float*)d_in[3];   // (H, 1)
    const float* W1     = (const float*)d_in[4];   // (H, H)
    float* out = (float*)d_out;                    // [alphat (T) | ct (H)]

    static int smem_set = 0;
    if (!smem_set) {
        cudaFuncSetAttribute(gemm_tanh_mma,
                             cudaFuncAttributeMaxDynamicSharedMemorySize, SMEM_GEMM);
        smem_set = 1;
    }

    proj_kernel<<<1, 256>>>(hc, W1);
    transpose_kernel<<<64, dim3(32, 8)>>>(Wm);
    gemm_tanh_mma<<<NB_G, 256, SMEM_GEMM>>>(inputs, V);
    ctred1_kernel<<<CTR1, 256>>>();                 // lse-independent
    softmax_part_kernel<<<SM_BLOCKS, 1024>>>();
    softmax_final_kernel<<<1, 32>>>();
    alpha_kernel<<<(T_CTX + 1023) / 1024, 1024>>>(out);
    ctred2_kernel<<<1, 256>>>(out + T_CTX);
}